// round 9
// baseline (speedup 1.0000x reference)
#include <cuda_runtime.h>

// Problem shapes (fixed by setup_inputs)
#define BN 64
#define VN 64
#define DN 64
#define HN 64
#define EN 4032     // V*(V-1)
#define ETN 2
#define OUTC (DN + HN)   // 128

// Node-factored first layer: A[b][v][h] = b1[1][h] + sum_d in[b][v][d]*W1[1][h][d]
//                            Bm[b][v][h] =            sum_d in[b][v][d]*W1[1][h][DN+d]
__device__ float g_A [BN * VN * HN];
__device__ float g_Bm[BN * VN * HN];

__device__ __forceinline__ unsigned f2tf32(float x) {
    unsigned r;
    asm("cvt.rna.tf32.f32 %0, %1;" : "=r"(r) : "f"(x));
    return r;
}
__device__ __forceinline__ void cp16(unsigned dst_smem, const void* src) {
    asm volatile("cp.async.ca.shared.global [%0], [%1], 16;"
                 :: "r"(dst_smem), "l"(src));
}
// Packed f32x2 add (sm_100+)
union F2U { float2 f; unsigned long long u; };
__device__ __forceinline__ float2 fadd2(float2 a, float2 b) {
    F2U x, y, r; x.f = a; y.f = b;
    asm("add.rn.f32x2 %0, %1, %2;" : "=l"(r.u) : "l"(x.u), "l"(y.u));
    return r.f;
}

// ---------------------------------------------------------------------------
// Kernel 1: node-factored layer-1 precompute (fp32 exact) + inputs copy.
// ---------------------------------------------------------------------------
__global__ __launch_bounds__(256)
void precompute_kernel(const float* __restrict__ inp,
                       const float* __restrict__ W1,
                       const float* __restrict__ b1,
                       float* __restrict__ out) {
    __shared__ __align__(16) float W1r[DN][68];
    __shared__ __align__(16) float W1s[DN][68];

    int b   = blockIdx.x;
    int v0  = blockIdx.y * 32;
    int tid = threadIdx.x;
    const float* inb = inp + b * VN * DN;

    for (int idx = tid; idx < 32 * DN; idx += 256) {
        int v = v0 + (idx >> 6), d = idx & 63;
        out[((size_t)(b * VN + v)) * OUTC + d] = inb[v * DN + d];
    }
    const float* W1e = W1 + HN * 2 * DN;  // edge type 1
    for (int idx = tid; idx < HN * 2 * DN; idx += 256) {
        int h = idx >> 7, d = idx & 127;
        float w = W1e[idx];
        if (d < DN) W1r[d][h] = w;
        else        W1s[d - DN][h] = w;
    }
    __syncthreads();

    int ty = tid >> 4, tx = tid & 15;
    float acc1[2][4], acc2[2][4];
    #pragma unroll
    for (int i = 0; i < 2; i++)
        #pragma unroll
        for (int j = 0; j < 4; j++) { acc1[i][j] = 0.f; acc2[i][j] = 0.f; }

    #pragma unroll 8
    for (int d = 0; d < DN; d++) {
        float xv[2];
        xv[0] = inb[(v0 + ty) * DN + d];
        xv[1] = inb[(v0 + ty + 16) * DN + d];
        float4 wr = *(const float4*)&W1r[d][4 * tx];
        float4 ws = *(const float4*)&W1s[d][4 * tx];
        #pragma unroll
        for (int i = 0; i < 2; i++) {
            acc1[i][0] += xv[i] * wr.x;  acc1[i][1] += xv[i] * wr.y;
            acc1[i][2] += xv[i] * wr.z;  acc1[i][3] += xv[i] * wr.w;
            acc2[i][0] += xv[i] * ws.x;  acc2[i][1] += xv[i] * ws.y;
            acc2[i][2] += xv[i] * ws.z;  acc2[i][3] += xv[i] * ws.w;
        }
    }
    float* Ab = g_A  + b * VN * HN;
    float* Bb = g_Bm + b * VN * HN;
    #pragma unroll
    for (int j = 0; j < 4; j++) {
        int h = 4 * tx + j;
        float bias = b1[HN + h];
        #pragma unroll
        for (int i = 0; i < 2; i++) {
            int v = v0 + ty + 16 * i;
            Ab[v * HN + h] = acc1[i][j] + bias;
            Bb[v * HN + h] = acc2[i][j];
        }
    }
}

// ---------------------------------------------------------------------------
// Kernel 2: transposed-GEMM edge MLP, occupancy-optimized.
// Block = (2 receivers) x (4 batches); grid 32 x 16 = 512 blocks.
// 8 warps: rl = w>>2 (receiver), ot = w&3 -> ONE m16 o-tile (obase=ot*16),
// covering ALL 64 senders (8 n-tiles) -> no cross-warp combine, direct store.
// W2 fragments (32 regs) register-stationary, permuted physical k
//   kphys = ctid*16 + 2*ks + half  (contiguous 64B per lane -> LDS.128).
// H built inline (packed fadd2 + fmax, raw fp32 to mma.tf32; W2 pre-scaled
// by 1+2^-11 to cancel truncation bias). 3 blocks/SM via launch_bounds.
// ---------------------------------------------------------------------------
__global__ __launch_bounds__(256, 3)
void edge_mma_kernel(const float* __restrict__ edges,
                     const float* __restrict__ W2,
                     const float* __restrict__ b2,
                     float* __restrict__ out) {
    __shared__ __align__(16) float Bs[2 * 4352];   // 2 x [64][68] Bm (swizzled chunks)
    __shared__ __align__(16) float As[2 * 128];    // 2 x [2][64] raw A rows
    __shared__ float wva[4 * 128];                 // edge weights, 4 batches

    int bbase = blockIdx.y * 4;
    int rbase = blockIdx.x * 2;
    int tid   = threadIdx.x;
    int w     = tid >> 5;
    int l     = tid & 31;
    int gid   = l >> 2;        // lane row-group
    int ctid  = l & 3;         // lane k-group
    int rl    = w >> 2;        // receiver within block
    int obase = (w & 3) * 16;  // this warp's o m-tile

    unsigned bsA = (unsigned)__cvta_generic_to_shared(Bs);
    unsigned asA = (unsigned)__cvta_generic_to_shared(As);

    // --- Issue cp.async for batch 0 into Bs buf0 (swizzled 16B chunks) ---
    {
        const float* src = g_Bm + (size_t)bbase * VN * HN;
        #pragma unroll
        for (int t = 0; t < 4; t++) {
            int c = tid + t * 256;            // 16B chunk id 0..1023
            int s = c >> 4, q = c & 15;
            int slot = q ^ ((q & 8) >> 2);
            cp16(bsA + (s * 68 + slot * 4) * 4, src + c * 4);
        }
        if (tid < 32)
            cp16(asA + tid * 16,
                 g_A + ((size_t)(bbase * VN + rbase)) * HN + tid * 4);
        asm volatile("cp.async.commit_group;");
    }

    // --- Stage W2[1]-tf32 into Bs buf1 (prologue only; freed before use).
    //     Pre-scale by (1+2^-11) to offset mma-input truncation of H. ---
    {
        const float* W2e = W2 + HN * HN;
        float* Wst = Bs + 4352;
        for (int idx = tid; idx < HN * HN; idx += 256) {
            int o = idx >> 6, kk = idx & 63;
            Wst[o * 68 + kk] =
                __uint_as_float(f2tf32(W2e[idx] * 1.00048828125f));
        }
    }

    // --- Prefetch 4 batches of edge weights (closed-form e(s,r)) ---
    for (int idx = tid; idx < 512; idx += 256) {
        int bi = idx >> 7, row = idx & 127;
        int srl = row >> 6, s = row & 63;
        int r = rbase + srl;
        float wgt = 0.f;
        if (s != r) {
            int e = s * 63 + r - (r > s ? 1 : 0);
            wgt = edges[((size_t)((bbase + bi) * EN + e)) * ETN + 1];
        }
        wva[idx] = wgt;
    }
    __syncthreads();

    // --- W2 A-fragments -> registers (ONE m-tile, 32 regs), permuted k ---
    unsigned a0r[8][4];
    float bias0, bias1;
    {
        const float* Wst = Bs + 4352;
        int p0 = (obase + gid) * 68 + ctid * 16;
        #pragma unroll
        for (int ks = 0; ks < 8; ks++) {
            float2 wa = *(const float2*)&Wst[p0 + 2 * ks];
            float2 wb = *(const float2*)&Wst[p0 + 8 * 68 + 2 * ks];
            a0r[ks][0] = __float_as_uint(wa.x);
            a0r[ks][2] = __float_as_uint(wa.y);
            a0r[ks][1] = __float_as_uint(wb.x);
            a0r[ks][3] = __float_as_uint(wb.y);
        }
        bias0 = b2[HN + obase + gid];
        bias1 = b2[HN + obase + 8 + gid];
    }

    // Swizzle fixup for this lane's chunk reads
    int kqx = (ctid >= 2) ? 2 : 0;

    int buf = 0;
    for (int bi = 0; bi < 4; bi++) {
        asm volatile("cp.async.wait_group 0;");
        __syncthreads();
        // batch bi in buf; all warps done reading buf^1 (last iter) and,
        // on bi==0, done extracting W2 frags from buf1.

        // Issue next batch's staging into buf^1 (overlaps compute)
        if (bi < 3) {
            const float* src = g_Bm + (size_t)(bbase + bi + 1) * VN * HN;
            unsigned dstB = bsA + (buf ^ 1) * 4352 * 4;
            #pragma unroll
            for (int t = 0; t < 4; t++) {
                int c = tid + t * 256;
                int s = c >> 4, q = c & 15;
                int slot = q ^ ((q & 8) >> 2);
                cp16(dstB + (s * 68 + slot * 4) * 4, src + c * 4);
            }
            if (tid < 32)
                cp16(asA + (buf ^ 1) * 512 + tid * 16,
                     g_A + ((size_t)((bbase + bi + 1) * VN + rbase)) * HN + tid * 4);
            asm volatile("cp.async.commit_group;");
        }

        // This lane's 16 A values (contiguous physical k run)
        float4 a4[4];
        {
            const float* Ar = As + buf * 128 + rl * 64 + ctid * 16;
            #pragma unroll
            for (int kq = 0; kq < 4; kq++)
                a4[kq] = *(const float4*)&Ar[kq * 4];
        }

        // mma over all 8 n-tiles (64 senders); even/odd-ks split accumulators
        float pa0 = 0.f, pa1 = 0.f;
        const float* wvb = wva + bi * 128 + rl * 64;
        const float* Bbase = Bs + buf * 4352;
        #pragma unroll
        for (int nt = 0; nt < 8; nt++) {
            const float* Br = Bbase + (nt * 8 + gid) * 68 + ctid * 16;
            float ce[4] = {0.f, 0.f, 0.f, 0.f};
            float co[4] = {0.f, 0.f, 0.f, 0.f};
            #pragma unroll
            for (int kq = 0; kq < 4; kq++) {
                float4 b4 = *(const float4*)&Br[(kq ^ kqx) * 4];
                // even ks = 2*kq: pair (x,y)
                float2 hv = fadd2(make_float2(a4[kq].x, a4[kq].y),
                                  make_float2(b4.x, b4.y));
                unsigned b0 = __float_as_uint(fmaxf(hv.x, 0.f));
                unsigned b1 = __float_as_uint(fmaxf(hv.y, 0.f));
                asm volatile(
                    "mma.sync.aligned.m16n8k8.row.col.f32.tf32.tf32.f32 "
                    "{%0,%1,%2,%3}, {%4,%5,%6,%7}, {%8,%9}, {%0,%1,%2,%3};"
                    : "+f"(ce[0]), "+f"(ce[1]), "+f"(ce[2]), "+f"(ce[3])
                    : "r"(a0r[2 * kq][0]), "r"(a0r[2 * kq][1]),
                      "r"(a0r[2 * kq][2]), "r"(a0r[2 * kq][3]),
                      "r"(b0), "r"(b1));
                // odd ks = 2*kq+1: pair (z,w)
                float2 hw = fadd2(make_float2(a4[kq].z, a4[kq].w),
                                  make_float2(b4.z, b4.w));
                unsigned b2r = __float_as_uint(fmaxf(hw.x, 0.f));
                unsigned b3r = __float_as_uint(fmaxf(hw.y, 0.f));
                asm volatile(
                    "mma.sync.aligned.m16n8k8.row.col.f32.tf32.tf32.f32 "
                    "{%0,%1,%2,%3}, {%4,%5,%6,%7}, {%8,%9}, {%0,%1,%2,%3};"
                    : "+f"(co[0]), "+f"(co[1]), "+f"(co[2]), "+f"(co[3])
                    : "r"(a0r[2 * kq + 1][0]), "r"(a0r[2 * kq + 1][1]),
                      "r"(a0r[2 * kq + 1][2]), "r"(a0r[2 * kq + 1][3]),
                      "r"(b2r), "r"(b3r));
            }
            int scol = nt * 8 + 2 * ctid;
            float w0 = wvb[scol], w1 = wvb[scol + 1];
            pa0 += w0 * fmaxf(ce[0] + co[0] + bias0, 0.f)
                 + w1 * fmaxf(ce[1] + co[1] + bias0, 0.f);
            pa1 += w0 * fmaxf(ce[2] + co[2] + bias1, 0.f)
                 + w1 * fmaxf(ce[3] + co[3] + bias1, 0.f);
        }
        // Reduce over the 4 sender-pair lane-groups; direct store
        pa0 += __shfl_xor_sync(0xFFFFFFFFu, pa0, 1);
        pa0 += __shfl_xor_sync(0xFFFFFFFFu, pa0, 2);
        pa1 += __shfl_xor_sync(0xFFFFFFFFu, pa1, 1);
        pa1 += __shfl_xor_sync(0xFFFFFFFFu, pa1, 2);
        if (ctid == 0) {
            float* dst = out + ((size_t)((bbase + bi) * VN + rbase + rl)) * OUTC + DN;
            dst[obase + gid]     = pa0;
            dst[obase + 8 + gid] = pa1;
        }
        buf ^= 1;
    }
}

// ---------------------------------------------------------------------------
// Launch
// ---------------------------------------------------------------------------
extern "C" void kernel_launch(void* const* d_in, const int* in_sizes, int n_in,
                              void* d_out, int out_size) {
    const float* inputs = (const float*)d_in[0];
    const float* edges  = (const float*)d_in[1];
    const float* W1     = (const float*)d_in[2];
    const float* b1     = (const float*)d_in[3];
    const float* W2     = (const float*)d_in[4];
    const float* b2     = (const float*)d_in[5];
    float* out = (float*)d_out;

    {
        dim3 grid(BN, 2);
        precompute_kernel<<<grid, 256>>>(inputs, W1, b1, out);
    }
    {
        dim3 grid(VN / 2, BN / 4);   // 32 x 16 = 512 blocks, 3/SM occupancy
        edge_mma_kernel<<<grid, 256>>>(edges, W2, b2, out);
    }
}